// round 6
// baseline (speedup 1.0000x reference)
#include <cuda_runtime.h>
#include <math.h>

#define NBITS   20
#define NSUB    ((1u << NBITS) - 1u)    // 1048575 elements in w
#define NT8     (1 << (NBITS - 3))      // 131072 threads, 8 elements each
#define NBLK    512
#define NTPB    256

// Per-block partial sums + arrival counter (counter reset by last block -> replay-safe).
__device__ float g_part[NBLK][NBITS + 1];
__device__ unsigned int g_count = 0;

__global__ void __launch_bounds__(NTPB) mil_fused_kernel(const float* __restrict__ w,
                                                         const float* __restrict__ yprob,
                                                         const int*   __restrict__ Yp,
                                                         int has_Y,
                                                         float* __restrict__ out) {
    const int tid = threadIdx.x;
    const int t   = blockIdx.x * NTPB + tid;    // chunk id, 0..131071 (exact cover)
    const int e0  = t << 3;                     // first element index of this chunk

    // ---- load 8 elements v[0..7] (e = e0+k), 2 x LDG.128 ----
    float v[8];
    const float4* __restrict__ w4 = (const float4*)w;
    if (t != NT8 - 1) {
        float4 a = w4[(e0 >> 2) + 0];
        float4 b = w4[(e0 >> 2) + 1];
        v[0]=a.x; v[1]=a.y; v[2]=a.z; v[3]=a.w;
        v[4]=b.x; v[5]=b.y; v[6]=b.z; v[7]=b.w;
    } else {
        // last chunk: e = 1048568..1048574 exist; e = 1048575 does not
        float4 a = w4[(e0 >> 2) + 0];
        v[0]=a.x; v[1]=a.y; v[2]=a.z; v[3]=a.w;
        v[4] = w[e0 + 4];
        v[5] = w[e0 + 5];
        v[6] = w[e0 + 6];
        v[7] = 0.0f;
    }

    // subset index of v[k] is i = e0+k+1 = 8t + (k+1).
    // v[0..6] have low-3-bit patterns 1..7 and high bits = bits of t.
    // v[7] has i = 8(t+1): low bits 0, high bits = bits of (t+1).
    const float v7 = v[7];

    // low-bit sums over v[0..6] (pattern j = k+1)
    const float B0 = (v[0] + v[2]) + (v[4] + v[6]);   // bit0: j in {1,3,5,7}
    const float B1 = (v[1] + v[2]) + (v[5] + v[6]);   // bit1: j in {2,3,6,7}
    const float B2 = (v[3] + v[4]) + (v[5] + v[6]);   // bit2: j in {4,5,6,7}
    // total of v[0..6] via clean pairwise tree (no shared subterms!)
    const float S  = ((v[0] + v[1]) + (v[2] + v[3])) + ((v[4] + v[5]) + v[6]);

    // ---- per-chunk contribution vector p[0..20] ----
    float p[NBITS + 1];
    p[0] = B0; p[1] = B1; p[2] = B2;
    p[NBITS] = S + v7;

    const unsigned tt = (unsigned)t;
    const unsigned t1 = (unsigned)t + 1u;   // t=NT8-1 -> v7==0, overflow pattern harmless
    const unsigned sb = __float_as_uint(S);
    const unsigned vb = __float_as_uint(v7);
#pragma unroll
    for (int b = 3; b < NBITS; b++) {
        const int sh = 34 - b;              // selects bit (b-3)
        unsigned m1 = (unsigned)(((int)(tt << sh)) >> 31);
        unsigned m2 = (unsigned)(((int)(t1 << sh)) >> 31);
        p[b] = __uint_as_float(sb & m1) + __uint_as_float(vb & m2);
    }

    // ---- block reduction of the 21-vector ----
    __shared__ float red[NTPB][NBITS + 2];   // +1 pad against systematic conflicts
#pragma unroll
    for (int b = 0; b <= NBITS; b++) red[tid][b] = p[b];
    __syncthreads();

#pragma unroll
    for (int s = NTPB / 2; s >= 1; s >>= 1) {
        if (tid < s) {
#pragma unroll
            for (int b = 0; b <= NBITS; b++) red[tid][b] += red[tid + s][b];
        }
        __syncthreads();
    }

    if (tid <= NBITS) g_part[blockIdx.x][tid] = red[0][tid];

    // ---- last-block-done: finalize inside the same launch ----
    __threadfence();
    __shared__ unsigned int s_last;
    if (tid == 0) s_last = atomicAdd(&g_count, 1u);
    __syncthreads();
    if (s_last != NBLK - 1) return;

    if (tid == 0) g_count = 0;              // reset for next graph replay
    __threadfence();

    // Parallel gather: thread tid sums rows tid and tid+256 (L2-resident).
    float r[NBITS + 1];
#pragma unroll
    for (int b = 0; b <= NBITS; b++)
        r[b] = g_part[tid][b] + g_part[tid + NTPB][b];
#pragma unroll
    for (int b = 0; b <= NBITS; b++) red[tid][b] = r[b];

    // fp32 logs in parallel (matches reference fp32 log)
    __shared__ float lp[NBITS], l1[NBITS];
    if (tid < NBITS) {
        float pp = yprob[tid];
        lp[tid] = logf(pp);
        l1[tid] = logf(1.0f - pp);
    }
    __syncthreads();

#pragma unroll
    for (int s = NTPB / 2; s >= 1; s >>= 1) {
        if (tid < s) {
#pragma unroll
            for (int b = 0; b <= NBITS; b++) red[tid][b] += red[tid + s][b];
        }
        __syncthreads();
    }

    if (tid == 0) {
        int y_nonzero = 1;
        if (has_Y) y_nonzero = (Yp[0] != 0);

        double basee = 0.0;
#pragma unroll
        for (int j = 0; j < NBITS; j++) basee += (double)l1[j];

        if (y_nonzero) {
            double res = basee * (double)red[0][NBITS];
#pragma unroll
            for (int b = 0; b < NBITS; b++) {
                int j = NBITS - 1 - b;   // column j <-> bit (NBITS-1-j) of subset index
                res += ((double)lp[j] - (double)l1[j]) * (double)red[0][b];
            }
            out[0] = (float)res;
        } else {
            out[0] = (float)((double)NSUB * basee);
        }
    }
}

extern "C" void kernel_launch(void* const* d_in, const int* in_sizes, int n_in,
                              void* d_out, int out_size) {
    const float* yprob = (const float*)d_in[0];
    const float* w     = (const float*)d_in[1];
    const int*   Yp    = (n_in >= 3) ? (const int*)d_in[2] : nullptr;
    float*       out   = (float*)d_out;
    (void)in_sizes; (void)out_size;

    mil_fused_kernel<<<NBLK, NTPB>>>(w, yprob, Yp, Yp != nullptr ? 1 : 0, out);
}

// round 7
// speedup vs baseline: 1.2161x; 1.2161x over previous
#include <cuda_runtime.h>
#include <math.h>

#define NBITS   20
#define NSUB    ((1u << NBITS) - 1u)    // 1048575 elements in w
#define NT8     (1 << (NBITS - 3))      // 131072 threads, 8 elements each
#define NBLK    512
#define NTPB    256
#define NWARP   (NTPB / 32)

// Per-block partial sums + arrival counter (counter reset by last block -> replay-safe).
__device__ float g_part[NBLK][NBITS + 1];
__device__ unsigned int g_count = 0;

__global__ void __launch_bounds__(NTPB) mil_fused_kernel(const float* __restrict__ w,
                                                         const float* __restrict__ yprob,
                                                         const int*   __restrict__ Yp,
                                                         int has_Y,
                                                         float* __restrict__ out) {
    const int tid  = threadIdx.x;
    const int warp = tid >> 5;
    const int lane = tid & 31;
    const int t    = blockIdx.x * NTPB + tid;   // chunk id, 0..131071 (exact cover)
    const int e0   = t << 3;                    // first element index of this chunk

    // ---- load 8 elements v[0..7] (e = e0+k), 2 x LDG.128 ----
    float v[8];
    const float4* __restrict__ w4 = (const float4*)w;
    if (t != NT8 - 1) {
        float4 a = w4[(e0 >> 2) + 0];
        float4 b = w4[(e0 >> 2) + 1];
        v[0]=a.x; v[1]=a.y; v[2]=a.z; v[3]=a.w;
        v[4]=b.x; v[5]=b.y; v[6]=b.z; v[7]=b.w;
    } else {
        // last chunk: e = 1048568..1048574 exist; e = 1048575 does not
        float4 a = w4[(e0 >> 2) + 0];
        v[0]=a.x; v[1]=a.y; v[2]=a.z; v[3]=a.w;
        v[4] = w[e0 + 4];
        v[5] = w[e0 + 5];
        v[6] = w[e0 + 6];
        v[7] = 0.0f;
    }

    // subset index of v[k] is i = e0+k+1 = 8t + (k+1).
    // v[0..6]: low-3-bit patterns 1..7, high bits = bits of t.
    // v[7]: i = 8(t+1): low bits 0, high bits = bits of (t+1).
    const float v7 = v[7];

    const float B0 = (v[0] + v[2]) + (v[4] + v[6]);   // bit0: j in {1,3,5,7}
    const float B1 = (v[1] + v[2]) + (v[5] + v[6]);   // bit1: j in {2,3,6,7}
    const float B2 = (v[3] + v[4]) + (v[5] + v[6]);   // bit2: j in {4,5,6,7}
    const float S  = ((v[0] + v[1]) + (v[2] + v[3])) + ((v[4] + v[5]) + v[6]);

    float p[NBITS + 1];
    p[0] = B0; p[1] = B1; p[2] = B2;
    p[NBITS] = S + v7;

    const unsigned tt = (unsigned)t;
    const unsigned t1 = (unsigned)t + 1u;   // t=NT8-1 -> v7==0, overflow pattern harmless
    const unsigned sb = __float_as_uint(S);
    const unsigned vb = __float_as_uint(v7);
#pragma unroll
    for (int b = 3; b < NBITS; b++) {
        const int sh = 34 - b;              // selects bit (b-3)
        unsigned m1 = (unsigned)(((int)(tt << sh)) >> 31);
        unsigned m2 = (unsigned)(((int)(t1 << sh)) >> 31);
        p[b] = __uint_as_float(sb & m1) + __uint_as_float(vb & m2);
    }

    // ---- warp butterfly reduction of the 21-vector (registers, no smem tree) ----
#pragma unroll
    for (int b = 0; b <= NBITS; b++) {
        float s = p[b];
#pragma unroll
        for (int o = 16; o > 0; o >>= 1)
            s += __shfl_xor_sync(0xFFFFFFFFu, s, o);
        p[b] = s;
    }

    __shared__ float sw[NWARP][NBITS + 1];
    if (lane == 0) {
#pragma unroll
        for (int b = 0; b <= NBITS; b++) sw[warp][b] = p[b];
    }
    __syncthreads();

    if (tid <= NBITS) {
        float a = sw[0][tid];
#pragma unroll
        for (int ww = 1; ww < NWARP; ww++) a += sw[ww][tid];
        g_part[blockIdx.x][tid] = a;
    }

    // ---- last-block-done: finalize inside the same launch ----
    __threadfence();
    __shared__ unsigned int s_last;
    if (tid == 0) s_last = atomicAdd(&g_count, 1u);
    __syncthreads();
    if (s_last != NBLK - 1) return;

    if (tid == 0) g_count = 0;              // reset for next graph replay
    __threadfence();

    // Parallel gather: thread tid sums rows tid and tid+256 (L2-resident).
    float r[NBITS + 1];
#pragma unroll
    for (int b = 0; b <= NBITS; b++)
        r[b] = g_part[tid][b] + g_part[tid + NTPB][b];

    // warp butterfly again
#pragma unroll
    for (int b = 0; b <= NBITS; b++) {
        float s = r[b];
#pragma unroll
        for (int o = 16; o > 0; o >>= 1)
            s += __shfl_xor_sync(0xFFFFFFFFu, s, o);
        r[b] = s;
    }
    if (lane == 0) {
#pragma unroll
        for (int b = 0; b <= NBITS; b++) sw[warp][b] = r[b];
    }

    // fp32 logs in parallel (matches reference fp32 log)
    __shared__ float lp[NBITS], l1[NBITS];
    __shared__ float sfin[NBITS + 1];
    if (tid < NBITS) {
        float pp = yprob[tid];
        lp[tid] = logf(pp);
        l1[tid] = logf(1.0f - pp);
    }
    __syncthreads();

    if (tid <= NBITS) {
        float a = sw[0][tid];
#pragma unroll
        for (int ww = 1; ww < NWARP; ww++) a += sw[ww][tid];
        sfin[tid] = a;
    }
    __syncthreads();

    if (tid == 0) {
        int y_nonzero = 1;
        if (has_Y) y_nonzero = (Yp[0] != 0);

        double basee = 0.0;
#pragma unroll
        for (int j = 0; j < NBITS; j++) basee += (double)l1[j];

        if (y_nonzero) {
            double res = basee * (double)sfin[NBITS];
#pragma unroll
            for (int b = 0; b < NBITS; b++) {
                int j = NBITS - 1 - b;   // column j <-> bit (NBITS-1-j) of subset index
                res += ((double)lp[j] - (double)l1[j]) * (double)sfin[b];
            }
            out[0] = (float)res;
        } else {
            out[0] = (float)((double)NSUB * basee);
        }
    }
}

extern "C" void kernel_launch(void* const* d_in, const int* in_sizes, int n_in,
                              void* d_out, int out_size) {
    const float* yprob = (const float*)d_in[0];
    const float* w     = (const float*)d_in[1];
    const int*   Yp    = (n_in >= 3) ? (const int*)d_in[2] : nullptr;
    float*       out   = (float*)d_out;
    (void)in_sizes; (void)out_size;

    mil_fused_kernel<<<NBLK, NTPB>>>(w, yprob, Yp, Yp != nullptr ? 1 : 0, out);
}

// round 8
// speedup vs baseline: 1.2187x; 1.0021x over previous
#include <cuda_runtime.h>
#include <math.h>

#define NBITS   20
#define NSUB    ((1u << NBITS) - 1u)    // 1048575 elements in w
#define NT8     (1 << (NBITS - 3))      // 131072 threads, 8 elements each
#define NBLK    512
#define NTPB    256
#define NWARP   (NTPB / 32)
#define FULLM   0xFFFFFFFFu

// Per-block partial sums + arrival counter (counter reset by last block -> replay-safe).
__device__ float g_part[NBLK][NBITS + 1];
__device__ unsigned int g_count = 0;

__global__ void __launch_bounds__(NTPB) mil_fused_kernel(const float* __restrict__ w,
                                                         const float* __restrict__ yprob,
                                                         const int*   __restrict__ Yp,
                                                         int has_Y,
                                                         float* __restrict__ out) {
    const int tid  = threadIdx.x;
    const int warp = tid >> 5;
    const int lane = tid & 31;
    const int t    = blockIdx.x * NTPB + tid;   // chunk id, 0..131071 (exact cover)
    const int e0   = t << 3;                    // first element index of this chunk

    // ---- load 8 elements v[0..7] (e = e0+k), 2 x LDG.128 ----
    float v[8];
    const float4* __restrict__ w4 = (const float4*)w;
    if (t != NT8 - 1) {
        float4 a = w4[(e0 >> 2) + 0];
        float4 b = w4[(e0 >> 2) + 1];
        v[0]=a.x; v[1]=a.y; v[2]=a.z; v[3]=a.w;
        v[4]=b.x; v[5]=b.y; v[6]=b.z; v[7]=b.w;
    } else {
        float4 a = w4[(e0 >> 2) + 0];
        v[0]=a.x; v[1]=a.y; v[2]=a.z; v[3]=a.w;
        v[4] = w[e0 + 4];
        v[5] = w[e0 + 5];
        v[6] = w[e0 + 6];
        v[7] = 0.0f;                    // i = 2^20 does not exist
    }

    // subset index of v[k] is i = 8t + (k+1).
    // v[0..6]: bits0-2 pattern = k+1, bits3-7 = lane, bits8-19 = cw   (t = 32*cw + lane)
    // v[7]:    i = 8(t+1): bits0-2 = 0; lanes 0..30: bits3-7 = lane+1, bits8+ = cw;
    //          lane 31:    bits3-7 = 0, bits8+ = cw+1.
    const float v7 = v[7];

    // bins 0..2 (bits 0-2 of i), per-thread
    float B0 = (v[0] + v[2]) + (v[4] + v[6]);
    float B1 = (v[1] + v[2]) + (v[5] + v[6]);
    float B2 = (v[3] + v[4]) + (v[5] + v[6]);
    const float S  = ((v[0] + v[1]) + (v[2] + v[3])) + ((v[4] + v[5]) + v[6]);

    // x_l: value whose bits3-7 pattern equals the lane id.
    float vs = __shfl_up_sync(FULLM, v7, 1);
    if (lane == 0) vs = 0.0f;
    float x = S + vs;
    const float v31 = __shfl_sync(FULLM, v7, 31);   // boundary element of the warp

    // ---- carry-accumulator butterfly: warp sum of x plus 5 lane-bit-masked sums ----
    float s = x, q;
    float A0, A1, A2, A3, A4;
    q = __shfl_xor_sync(FULLM, s, 1);  A0 = (lane & 1)  ? s : q;  s += q;
    q = __shfl_xor_sync(FULLM, s, 2);  A1 = (lane & 2)  ? s : q;  s += q;
    A0 += __shfl_xor_sync(FULLM, A0, 2);
    q = __shfl_xor_sync(FULLM, s, 4);  A2 = (lane & 4)  ? s : q;  s += q;
    A0 += __shfl_xor_sync(FULLM, A0, 4);
    A1 += __shfl_xor_sync(FULLM, A1, 4);
    q = __shfl_xor_sync(FULLM, s, 8);  A3 = (lane & 8)  ? s : q;  s += q;
    A0 += __shfl_xor_sync(FULLM, A0, 8);
    A1 += __shfl_xor_sync(FULLM, A1, 8);
    A2 += __shfl_xor_sync(FULLM, A2, 8);
    q = __shfl_xor_sync(FULLM, s, 16); A4 = (lane & 16) ? s : q;  s += q;
    A0 += __shfl_xor_sync(FULLM, A0, 16);
    A1 += __shfl_xor_sync(FULLM, A1, 16);
    A2 += __shfl_xor_sync(FULLM, A2, 16);
    A3 += __shfl_xor_sync(FULLM, A3, 16);
    const float W = s;        // = warpSumAll - v31 (v31's value was shifted out)

    // plain butterflies for bins 0..2
#pragma unroll
    for (int o = 16; o > 0; o >>= 1) B0 += __shfl_xor_sync(FULLM, B0, o);
#pragma unroll
    for (int o = 16; o > 0; o >>= 1) B1 += __shfl_xor_sync(FULLM, B1, o);
#pragma unroll
    for (int o = 16; o > 0; o >>= 1) B2 += __shfl_xor_sync(FULLM, B2, o);

    // ---- per-warp 21-vector; lane l computes bin l ----
    const unsigned cw  = (unsigned)(blockIdx.x * NWARP + warp);   // bits 8-19 of i for in-warp elems
    const unsigned cw1 = cw + 1u;                                  // ... for the warp-boundary elem
    __shared__ float sw[NWARP][NBITS + 1];
    if (lane <= NBITS) {
        float val;
        if      (lane == 0) val = B0;
        else if (lane == 1) val = B1;
        else if (lane == 2) val = B2;
        else if (lane == 3) val = A0;
        else if (lane == 4) val = A1;
        else if (lane == 5) val = A2;
        else if (lane == 6) val = A3;
        else if (lane == 7) val = A4;
        else if (lane < NBITS) {
            const int bb = lane - 8;                   // bit bb of cw / cw1
            val = ((cw  >> bb) & 1u ? W   : 0.0f)
                + ((cw1 >> bb) & 1u ? v31 : 0.0f);
        } else {
            val = W + v31;                              // bin 20: total sum
        }
        sw[warp][lane] = val;
    }
    __syncthreads();

    if (tid <= NBITS) {
        float a = sw[0][tid];
#pragma unroll
        for (int ww = 1; ww < NWARP; ww++) a += sw[ww][tid];
        g_part[blockIdx.x][tid] = a;
    }
    __syncthreads();

    // ---- last-block-done: fence/atomic by ONE thread per block ----
    __shared__ unsigned int s_last;
    if (tid == 0) {
        __threadfence();                       // publish this block's g_part row
        s_last = atomicAdd(&g_count, 1u);
    }
    __syncthreads();
    if (s_last != NBLK - 1) return;

    if (tid == 0) {
        g_count = 0;                           // reset for next graph replay
        __threadfence();                       // acquire side
    }
    __syncthreads();

    // ---- finalize: gather 512 rows with high MLP, warp-butterfly, epilogue ----
    float r[NBITS + 1];
#pragma unroll
    for (int b = 0; b <= NBITS; b++)
        r[b] = g_part[tid][b] + g_part[tid + NTPB][b];

#pragma unroll
    for (int b = 0; b <= NBITS; b++) {
        float z = r[b];
#pragma unroll
        for (int o = 16; o > 0; o >>= 1) z += __shfl_xor_sync(FULLM, z, o);
        r[b] = z;
    }
    if (lane == 0) {
#pragma unroll
        for (int b = 0; b <= NBITS; b++) sw[warp][b] = r[b];
    }

    __shared__ float lp[NBITS], l1[NBITS], sfin[NBITS + 1];
    if (tid < NBITS) {
        float pp = yprob[tid];
        lp[tid] = logf(pp);
        l1[tid] = logf(1.0f - pp);
    }
    __syncthreads();

    if (tid <= NBITS) {
        float a = sw[0][tid];
#pragma unroll
        for (int ww = 1; ww < NWARP; ww++) a += sw[ww][tid];
        sfin[tid] = a;
    }
    __syncthreads();

    if (tid == 0) {
        int y_nonzero = 1;
        if (has_Y) y_nonzero = (Yp[0] != 0);

        double basee = 0.0;
#pragma unroll
        for (int j = 0; j < NBITS; j++) basee += (double)l1[j];

        if (y_nonzero) {
            double res = basee * (double)sfin[NBITS];
#pragma unroll
            for (int b = 0; b < NBITS; b++) {
                int j = NBITS - 1 - b;     // column j <-> bit (NBITS-1-j) of subset index
                res += ((double)lp[j] - (double)l1[j]) * (double)sfin[b];
            }
            out[0] = (float)res;
        } else {
            out[0] = (float)((double)NSUB * basee);
        }
    }
}

extern "C" void kernel_launch(void* const* d_in, const int* in_sizes, int n_in,
                              void* d_out, int out_size) {
    const float* yprob = (const float*)d_in[0];
    const float* w     = (const float*)d_in[1];
    const int*   Yp    = (n_in >= 3) ? (const int*)d_in[2] : nullptr;
    float*       out   = (float*)d_out;
    (void)in_sizes; (void)out_size;

    mil_fused_kernel<<<NBLK, NTPB>>>(w, yprob, Yp, Yp != nullptr ? 1 : 0, out);
}